// round 13
// baseline (speedup 1.0000x reference)
#include <cuda_runtime.h>
#include <cuda_bf16.h>
#include <cuda_fp16.h>
#include <math.h>

// Problem dims (fixed by the dataset)
#define BB  4
#define SS  2048
#define DD  512
#define HH  8
#define HD  64
#define MM  (BB*SS)          // 8192
#define NKBI 16              // k-tiles per attention row strip (2048/128)

// Scratch (allocation-free rule: __device__ globals)
__device__ __align__(16) __nv_bfloat16 g_qh[(size_t)MM * DD];
__device__ __align__(16) __nv_bfloat16 g_ql[(size_t)MM * DD];
__device__ __align__(16) __nv_bfloat16 g_kh[(size_t)MM * DD];
__device__ __align__(16) __nv_bfloat16 g_kl[(size_t)MM * DD];
__device__ __align__(16) __half g_vh[(size_t)MM * DD];            // fp16 V
__device__ float  g_ctx [(size_t)MM * DD];
__device__ __align__(16) __half g_p[(size_t)BB * HH * SS * SS];   // fp16 exp(scores), 268MB
__device__ float  g_psum[(size_t)BB * HH * SS];                   // full row sums

// ---------------------------------------------------------------------------
// helpers
// ---------------------------------------------------------------------------
__device__ __forceinline__ void split2(float x0, float x1, unsigned& h, unsigned& l)
{
    __nv_bfloat162 hb = __floats2bfloat162_rn(x0, x1);
    float2 hf = __bfloat1622float2(hb);
    __nv_bfloat162 lb = __floats2bfloat162_rn(x0 - hf.x, x1 - hf.y);
    h = *reinterpret_cast<unsigned*>(&hb);
    l = *reinterpret_cast<unsigned*>(&lb);
}

__device__ __forceinline__ void mma16816(float c[4],
    unsigned a0, unsigned a1, unsigned a2, unsigned a3,
    unsigned b0, unsigned b1)
{
    asm volatile(
        "mma.sync.aligned.m16n8k16.row.col.f32.bf16.bf16.f32 "
        "{%0,%1,%2,%3},{%4,%5,%6,%7},{%8,%9},{%0,%1,%2,%3};"
        : "+f"(c[0]), "+f"(c[1]), "+f"(c[2]), "+f"(c[3])
        : "r"(a0), "r"(a1), "r"(a2), "r"(a3), "r"(b0), "r"(b1));
}
__device__ __forceinline__ void mma16816_f16(float c[4],
    unsigned a0, unsigned a1, unsigned a2, unsigned a3,
    unsigned b0, unsigned b1)
{
    asm volatile(
        "mma.sync.aligned.m16n8k16.row.col.f32.f16.f16.f32 "
        "{%0,%1,%2,%3},{%4,%5,%6,%7},{%8,%9},{%0,%1,%2,%3};"
        : "+f"(c[0]), "+f"(c[1]), "+f"(c[2]), "+f"(c[3])
        : "r"(a0), "r"(a1), "r"(a2), "r"(a3), "r"(b0), "r"(b1));
}
__device__ __forceinline__ unsigned smem_u32(const void* p)
{
    return (unsigned)__cvta_generic_to_shared(p);
}
__device__ __forceinline__ void ldsm_x4(unsigned& r0, unsigned& r1,
                                        unsigned& r2, unsigned& r3, unsigned a)
{
    asm volatile("ldmatrix.sync.aligned.m8n8.x4.shared.b16 {%0,%1,%2,%3}, [%4];"
        : "=r"(r0), "=r"(r1), "=r"(r2), "=r"(r3) : "r"(a));
}
__device__ __forceinline__ void ldsm_x4_t(unsigned& r0, unsigned& r1,
                                          unsigned& r2, unsigned& r3, unsigned a)
{
    asm volatile("ldmatrix.sync.aligned.m8n8.x4.trans.shared.b16 {%0,%1,%2,%3}, [%4];"
        : "=r"(r0), "=r"(r1), "=r"(r2), "=r"(r3) : "r"(a));
}
__device__ __forceinline__ void cp16(unsigned dst, const void* src)
{
    asm volatile("cp.async.cg.shared.global [%0], [%1], 16;" :: "r"(dst), "l"(src));
}
__device__ __forceinline__ void cp_commit()
{
    asm volatile("cp.async.commit_group;");
}
template<int N> __device__ __forceinline__ void cp_wait()
{
    asm volatile("cp.async.wait_group %0;" :: "n"(N));
}

// ---------------------------------------------------------------------------
// Projection GEMM (unchanged from round 11): BM=128, BN=64, BKT=32, ldsm.
// ---------------------------------------------------------------------------
#define PJ_LDA 40
#define PJ_LDB 72
#define PJ_A_STAGE (128 * PJ_LDA)
#define PJ_B_STAGE (32 * PJ_LDB)
#define PJ_SMEM ((2*PJ_A_STAGE*2 + 2*PJ_B_STAGE*2) * 2)

template<bool OUT_PROJ>
__global__ void __launch_bounds__(256, 2)
proj_gemm(const float* __restrict__ A,
          const float* __restrict__ W0, const float* __restrict__ W1,
          const float* __restrict__ W2,
          const float* __restrict__ b0, const float* __restrict__ b1,
          const float* __restrict__ b2,
          float* __restrict__ outf)
{
    extern __shared__ __align__(16) char pmem[];
    __nv_bfloat16* Ah = (__nv_bfloat16*)pmem;
    __nv_bfloat16* Al = Ah + 2 * PJ_A_STAGE;
    __nv_bfloat16* Bh = Al + 2 * PJ_A_STAGE;
    __nv_bfloat16* Bl = Bh + 2 * PJ_B_STAGE;

    const int zz = blockIdx.z;
    const float* B    = (zz == 0) ? W0 : (zz == 1) ? W1 : W2;
    const float* bias = (zz == 0) ? b0 : (zz == 1) ? b1 : b2;

    const int tid   = threadIdx.x;
    const int warp  = tid >> 5;
    const int lane  = tid & 31;
    const int g     = lane >> 2;
    const int tq    = lane & 3;
    const int warpM = warp >> 2;
    const int warpN = warp & 3;
    const int m0    = blockIdx.y * 128;
    const int n0    = blockIdx.x * 64;

    const int a_row = (lane & 7) + ((lane >> 3) & 1) * 8;
    const int a_col = (lane >> 4) * 8;
    const int b_krw = a_row;
    const int b_col = warpN * 16 + (lane >> 4) * 8;

    float acc[4][2][4] = {};
    float4 pa[4], pb[2];

    auto load_t = [&](int kt) {
        #pragma unroll
        for (int j = 0; j < 4; j++) {
            int idx = tid + j * 256;
            int r = idx >> 3;
            int c = (idx & 7) << 2;
            pa[j] = *(const float4*)&A[(size_t)(m0 + r) * DD + kt + c];
        }
        #pragma unroll
        for (int j = 0; j < 2; j++) {
            int idx = tid + j * 256;
            int k = idx >> 4;
            int c = (idx & 15) << 2;
            pb[j] = *(const float4*)&B[(size_t)(kt + k) * DD + n0 + c];
        }
    };
    auto store_t = [&](int s) {
        __nv_bfloat16* Aph = Ah + s * PJ_A_STAGE;
        __nv_bfloat16* Apl = Al + s * PJ_A_STAGE;
        __nv_bfloat16* Bph = Bh + s * PJ_B_STAGE;
        __nv_bfloat16* Bpl = Bl + s * PJ_B_STAGE;
        #pragma unroll
        for (int j = 0; j < 4; j++) {
            int idx = tid + j * 256;
            int r = idx >> 3;
            int c = (idx & 7) << 2;
            unsigned h01, l01, h23, l23;
            split2(pa[j].x, pa[j].y, h01, l01);
            split2(pa[j].z, pa[j].w, h23, l23);
            *(unsigned*)&Aph[r * PJ_LDA + c]     = h01;
            *(unsigned*)&Aph[r * PJ_LDA + c + 2] = h23;
            *(unsigned*)&Apl[r * PJ_LDA + c]     = l01;
            *(unsigned*)&Apl[r * PJ_LDA + c + 2] = l23;
        }
        #pragma unroll
        for (int j = 0; j < 2; j++) {
            int idx = tid + j * 256;
            int k = idx >> 4;
            int c = (idx & 15) << 2;
            unsigned h01, l01, h23, l23;
            split2(pb[j].x, pb[j].y, h01, l01);
            split2(pb[j].z, pb[j].w, h23, l23);
            *(unsigned*)&Bph[k * PJ_LDB + c]     = h01;
            *(unsigned*)&Bph[k * PJ_LDB + c + 2] = h23;
            *(unsigned*)&Bpl[k * PJ_LDB + c]     = l01;
            *(unsigned*)&Bpl[k * PJ_LDB + c + 2] = l23;
        }
    };

    const int NKT = DD / 32;
    load_t(0);
    store_t(0);
    load_t(32);
    __syncthreads();

    for (int kt = 0; kt < NKT; kt++) {
        const int buf = kt & 1;
        if (kt + 1 < NKT) store_t(buf ^ 1);
        if (kt + 2 < NKT) load_t((kt + 2) * 32);

        const __nv_bfloat16* Aph = Ah + buf * PJ_A_STAGE;
        const __nv_bfloat16* Apl = Al + buf * PJ_A_STAGE;
        const __nv_bfloat16* Bph = Bh + buf * PJ_B_STAGE;
        const __nv_bfloat16* Bpl = Bl + buf * PJ_B_STAGE;

        #pragma unroll
        for (int ks = 0; ks < 2; ks++) {
            const int k0 = ks * 16;
            unsigned afh[4][4], afl[4][4], bfh[2][2], bfl[2][2];
            #pragma unroll
            for (int mt = 0; mt < 4; mt++) {
                int row = warpM * 64 + mt * 16 + a_row;
                ldsm_x4(afh[mt][0], afh[mt][1], afh[mt][2], afh[mt][3],
                        smem_u32(&Aph[row * PJ_LDA + k0 + a_col]));
                ldsm_x4(afl[mt][0], afl[mt][1], afl[mt][2], afl[mt][3],
                        smem_u32(&Apl[row * PJ_LDA + k0 + a_col]));
            }
            ldsm_x4_t(bfh[0][0], bfh[0][1], bfh[1][0], bfh[1][1],
                      smem_u32(&Bph[(k0 + b_krw) * PJ_LDB + b_col]));
            ldsm_x4_t(bfl[0][0], bfl[0][1], bfl[1][0], bfl[1][1],
                      smem_u32(&Bpl[(k0 + b_krw) * PJ_LDB + b_col]));

            #pragma unroll
            for (int mt = 0; mt < 4; mt++)
                #pragma unroll
                for (int nt = 0; nt < 2; nt++) {
                    mma16816(acc[mt][nt], afh[mt][0], afh[mt][1], afh[mt][2], afh[mt][3],
                             bfh[nt][0], bfh[nt][1]);
                    mma16816(acc[mt][nt], afh[mt][0], afh[mt][1], afh[mt][2], afh[mt][3],
                             bfl[nt][0], bfl[nt][1]);
                    mma16816(acc[mt][nt], afl[mt][0], afl[mt][1], afl[mt][2], afl[mt][3],
                             bfh[nt][0], bfh[nt][1]);
                }
        }
        __syncthreads();
    }

    #pragma unroll
    for (int mt = 0; mt < 4; mt++) {
        int r0 = m0 + warpM * 64 + mt * 16 + g;
        #pragma unroll
        for (int nt = 0; nt < 2; nt++) {
            int c = n0 + warpN * 16 + nt * 8 + 2 * tq;
            float bx = bias[c], by = bias[c + 1];
            float v00 = acc[mt][nt][0] + bx, v01 = acc[mt][nt][1] + by;
            float v10 = acc[mt][nt][2] + bx, v11 = acc[mt][nt][3] + by;
            size_t i0 = (size_t)r0 * DD + c;
            size_t i1 = (size_t)(r0 + 8) * DD + c;
            if (OUT_PROJ) {
                *(float2*)&outf[i0] = make_float2(v00, v01);
                *(float2*)&outf[i1] = make_float2(v10, v11);
            } else if (zz == 2) {
                *(__half2*)&g_vh[i0] = __floats2half2_rn(v00, v01);
                *(__half2*)&g_vh[i1] = __floats2half2_rn(v10, v11);
            } else {
                __nv_bfloat16* Oh = (zz == 0) ? g_qh : g_kh;
                __nv_bfloat16* Ol = (zz == 0) ? g_ql : g_kl;
                unsigned h0, l0, h1, l1;
                split2(v00, v01, h0, l0);
                split2(v10, v11, h1, l1);
                *(unsigned*)&Oh[i0] = h0;  *(unsigned*)&Ol[i0] = l0;
                *(unsigned*)&Oh[i1] = h1;  *(unsigned*)&Ol[i1] = l1;
            }
        }
    }
}

// ---------------------------------------------------------------------------
// FUSED scores+ctx: one CTA per (z, 128-q-row strip), loops 16 k-tiles.
// Per tile: scores MMA (bf16x3) -> exp -> E to smem stage -> E gmem writeout
// + ctx MMA (fp16, A-frags from stage) -> cp.async prefetch of K/V.
// Full row sums accumulated in regs; ctx normalized in epilogue.
// ---------------------------------------------------------------------------
#define FL_LD   72                      // K/V/Q row pitch (halves)
#define FL_ELD  136                     // E stage row pitch (halves)
#define FL_T    (128 * FL_LD)           // halves per tile
// smem halves: Qh,Ql (2*FL_T) + Kh,Kl (2 stages each: 4*FL_T) + Vs (2*FL_T) + Es
#define FL_Q_OFF   0
#define FL_K_OFF   (2 * FL_T)
#define FL_V_OFF   (6 * FL_T)
#define FL_E_OFF   (8 * FL_T)
#define FL_E_SZ    (128 * FL_ELD)
#define FL_RED_OFF ((FL_E_OFF + FL_E_SZ) * 2)            // byte offset of srow
#define FL_SMEM    (FL_RED_OFF + 128 * 5 * 4 + 128 * 4)  // + srow + sInv

__global__ void __launch_bounds__(256, 1)
attn_fused(float* __restrict__ dummy)
{
    extern __shared__ __align__(16) char fmem[];
    __nv_bfloat16* Qh = (__nv_bfloat16*)fmem;
    __nv_bfloat16* Ql = Qh + FL_T;
    __nv_bfloat16* Kh = (__nv_bfloat16*)fmem + FL_K_OFF;   // [2][FL_T]
    __nv_bfloat16* Kl = Kh + 2 * FL_T;
    __half*        Vs = (__half*)fmem + FL_V_OFF;          // [2][FL_T]
    __half*        Es = (__half*)fmem + FL_E_OFF;
    float (*srow)[5]  = (float(*)[5])(fmem + FL_RED_OFF);
    float* sInv       = (float*)(fmem + FL_RED_OFF + 128 * 5 * 4);

    const int z = blockIdx.y;
    const int b = z >> 3, h = z & 7;
    const int m0 = blockIdx.x * 128;
    const size_t qoff = ((size_t)(b * SS + m0)) * DD + h * HD;
    const size_t kbase = ((size_t)b * SS) * DD + h * HD;

    const int tid   = threadIdx.x;
    const int warp  = tid >> 5;
    const int lane  = tid & 31;
    const int g     = lane >> 2;
    const int tq    = lane & 3;
    const int warpM = warp >> 2;
    const int warpN = warp & 3;

    const int a_row = (lane & 7) + ((lane >> 3) & 1) * 8;
    const int a_col = (lane >> 4) * 8;
    const int b_krw = a_row;
    const int v_col = warpN * 16 + (lane >> 4) * 8;

    // cp.async stage loader: K hi/lo + V tile for k-tile kt -> stage s
    const int ld_r = tid >> 3;             // row 0..31 per 256-thread pass
    const int ld_c = (tid & 7) << 3;       // col (halves)
    auto issue_stage = [&](int kt, int s) {
        const size_t off = kbase + (size_t)(kt * 128) * DD;
        #pragma unroll
        for (int j = 0; j < 4; j++) {
            int r = ld_r + j * 32;
            cp16(smem_u32(&Kh[s * FL_T + r * FL_LD + ld_c]),
                 &g_kh[off + (size_t)r * DD + ld_c]);
            cp16(smem_u32(&Kl[s * FL_T + r * FL_LD + ld_c]),
                 &g_kl[off + (size_t)r * DD + ld_c]);
            cp16(smem_u32(&Vs[s * FL_T + r * FL_LD + ld_c]),
                 &g_vh[off + (size_t)r * DD + ld_c]);
        }
        cp_commit();
    };

    // prolog: stages 0,1 in flight; Q tile staged directly
    issue_stage(0, 0);
    issue_stage(1, 1);
    #pragma unroll
    for (int j = 0; j < 4; j++) {
        int r = ld_r + j * 32;
        *(uint4*)&Qh[r * FL_LD + ld_c] = *(const uint4*)&g_qh[qoff + (size_t)r * DD + ld_c];
        *(uint4*)&Ql[r * FL_LD + ld_c] = *(const uint4*)&g_ql[qoff + (size_t)r * DD + ld_c];
    }

    float ctx[4][2][4] = {};
    float sAcc[4][2] = {};
    __half* Ez = g_p + (size_t)z * SS * SS;

    for (int kt = 0; kt < NKBI; kt++) {
        const int buf = kt & 1;
        cp_wait<1>();
        __syncthreads();

        const __nv_bfloat16* Kph = Kh + buf * FL_T;
        const __nv_bfloat16* Kpl = Kl + buf * FL_T;

        // ---- scores MMA: acc[4][4][4] ----
        float acc[4][4][4] = {};
        #pragma unroll
        for (int ks = 0; ks < 4; ks++) {
            const int k0 = ks * 16;
            unsigned afh[4][4], afl[4][4], bfh[4][2], bfl[4][2];
            #pragma unroll
            for (int mt = 0; mt < 4; mt++) {
                int row = warpM * 64 + mt * 16 + a_row;
                ldsm_x4(afh[mt][0], afh[mt][1], afh[mt][2], afh[mt][3],
                        smem_u32(&Qh[row * FL_LD + k0 + a_col]));
                ldsm_x4(afl[mt][0], afl[mt][1], afl[mt][2], afl[mt][3],
                        smem_u32(&Ql[row * FL_LD + k0 + a_col]));
            }
            #pragma unroll
            for (int ng = 0; ng < 2; ng++) {
                int nrow = warpN * 32 + ng * 16 + a_row;
                ldsm_x4(bfh[2*ng][0], bfh[2*ng+1][0], bfh[2*ng][1], bfh[2*ng+1][1],
                        smem_u32(&Kph[nrow * FL_LD + k0 + a_col]));
                ldsm_x4(bfl[2*ng][0], bfl[2*ng+1][0], bfl[2*ng][1], bfl[2*ng+1][1],
                        smem_u32(&Kpl[nrow * FL_LD + k0 + a_col]));
            }
            #pragma unroll
            for (int mt = 0; mt < 4; mt++)
                #pragma unroll
                for (int nt = 0; nt < 4; nt++) {
                    mma16816(acc[mt][nt], afh[mt][0], afh[mt][1], afh[mt][2], afh[mt][3],
                             bfh[nt][0], bfh[nt][1]);
                    mma16816(acc[mt][nt], afh[mt][0], afh[mt][1], afh[mt][2], afh[mt][3],
                             bfl[nt][0], bfl[nt][1]);
                    mma16816(acc[mt][nt], afl[mt][0], afl[mt][1], afl[mt][2], afl[mt][3],
                             bfh[nt][0], bfh[nt][1]);
                }
        }

        // ---- exp, row-sum accumulate, E -> smem stage ----
        #pragma unroll
        for (int mt = 0; mt < 4; mt++) {
            int rl = warpM * 64 + mt * 16 + g;
            #pragma unroll
            for (int nt = 0; nt < 4; nt++) {
                int c = warpN * 32 + nt * 8 + 2 * tq;
                float e0 = __expf(acc[mt][nt][0] * 0.125f);
                float e1 = __expf(acc[mt][nt][1] * 0.125f);
                float e2 = __expf(acc[mt][nt][2] * 0.125f);
                float e3 = __expf(acc[mt][nt][3] * 0.125f);
                sAcc[mt][0] += e0 + e1;
                sAcc[mt][1] += e2 + e3;
                *(__half2*)&Es[rl * FL_ELD + c]       = __floats2half2_rn(e0, e1);
                *(__half2*)&Es[(rl + 8) * FL_ELD + c] = __floats2half2_rn(e2, e3);
            }
        }
        __syncthreads();

        // ---- E writeout to gmem (coalesced uint4) ----
        {
            const int n0 = kt * 128;
            #pragma unroll
            for (int j = 0; j < 8; j++) {
                int idx = tid + j * 256;       // 2048 uint4
                int r = idx >> 4;
                int c = (idx & 15) << 3;
                *(uint4*)&Ez[(size_t)(m0 + r) * SS + n0 + c] =
                    *(uint4*)&Es[r * FL_ELD + c];
            }
        }

        // ---- ctx MMA: A from Es, B (V) from stage ----
        const __half* Vp = Vs + buf * FL_T;
        #pragma unroll
        for (int ks = 0; ks < 8; ks++) {
            const int k0 = ks * 16;
            unsigned af[4][4], bf[2][2];
            #pragma unroll
            for (int mt = 0; mt < 4; mt++) {
                int row = warpM * 64 + mt * 16 + a_row;
                ldsm_x4(af[mt][0], af[mt][1], af[mt][2], af[mt][3],
                        smem_u32(&Es[row * FL_ELD + k0 + a_col]));
            }
            ldsm_x4_t(bf[0][0], bf[0][1], bf[1][0], bf[1][1],
                      smem_u32(&Vp[(k0 + b_krw) * FL_LD + v_col]));
            #pragma unroll
            for (int mt = 0; mt < 4; mt++)
                #pragma unroll
                for (int nt = 0; nt < 2; nt++)
                    mma16816_f16(ctx[mt][nt], af[mt][0], af[mt][1], af[mt][2], af[mt][3],
                                 bf[nt][0], bf[nt][1]);
        }
        __syncthreads();

        if (kt + 2 < NKBI) issue_stage(kt + 2, buf);
        else cp_commit();     // keep group accounting uniform
    }

    // ---- epilogue: row sums -> sInv + g_psum; normalized ctx writeout ----
    #pragma unroll
    for (int mt = 0; mt < 4; mt++) {
        int rl = warpM * 64 + mt * 16 + g;
        float sA = sAcc[mt][0], sB = sAcc[mt][1];
        sA += __shfl_xor_sync(0xffffffffu, sA, 1);
        sA += __shfl_xor_sync(0xffffffffu, sA, 2);
        sB += __shfl_xor_sync(0xffffffffu, sB, 1);
        sB += __shfl_xor_sync(0xffffffffu, sB, 2);
        if (tq == 0) {
            srow[rl][warpN]     = sA;
            srow[rl + 8][warpN] = sB;
        }
    }
    __syncthreads();
    if (tid < 128) {
        float s = srow[tid][0] + srow[tid][1] + srow[tid][2] + srow[tid][3];
        sInv[tid] = 1.f / s;
        g_psum[(size_t)z * SS + m0 + tid] = s;
    }
    __syncthreads();

    float* C = g_ctx + (size_t)(b * SS + m0) * DD + h * HD;
    #pragma unroll
    for (int mt = 0; mt < 4; mt++) {
        int rl = warpM * 64 + mt * 16 + g;
        float iv0 = sInv[rl];
        float iv1 = sInv[rl + 8];
        #pragma unroll
        for (int nt = 0; nt < 2; nt++) {
            int c = warpN * 16 + nt * 8 + 2 * tq;
            *(float2*)&C[(size_t)rl * DD + c] =
                make_float2(ctx[mt][nt][0] * iv0, ctx[mt][nt][1] * iv0);
            *(float2*)&C[(size_t)(rl + 8) * DD + c] =
                make_float2(ctx[mt][nt][2] * iv1, ctx[mt][nt][3] * iv1);
        }
    }
}

// ---------------------------------------------------------------------------
// avg_attn: per (b,q) row, avg_h E[z][q][:] / (8 * S[z][q]).
// ---------------------------------------------------------------------------
__global__ void __launch_bounds__(256)
avg_kernel(float* __restrict__ avg_out)
{
    const int q = blockIdx.x;
    const int b = blockIdx.y;
    const int tid = threadIdx.x;

    __shared__ float sInv[HH];
    if (tid < HH)
        sInv[tid] = 0.125f / g_psum[(size_t)(b * HH + tid) * SS + q];
    __syncthreads();

    const int c0 = tid * 8;
    float av[8] = {};
    #pragma unroll
    for (int h = 0; h < HH; h++) {
        const __half* E = g_p + ((size_t)(b * HH + h) * SS + q) * SS;
        float inv = sInv[h];
        uint4 v = *(const uint4*)&E[c0];
        const __half2* hp = (const __half2*)&v;
        #pragma unroll
        for (int j = 0; j < 4; j++) {
            float2 f = __half22float2(hp[j]);
            av[2*j]   += f.x * inv;
            av[2*j+1] += f.y * inv;
        }
    }
    float* arow = avg_out + ((size_t)b * SS + q) * SS;
    *(float4*)&arow[c0]     = make_float4(av[0], av[1], av[2], av[3]);
    *(float4*)&arow[c0 + 4] = make_float4(av[4], av[5], av[6], av[7]);
}

// ---------------------------------------------------------------------------
extern "C" void kernel_launch(void* const* d_in, const int* in_sizes, int n_in,
                              void* d_out, int out_size)
{
    const float* x  = (const float*)d_in[0];
    const float* Wq = (const float*)d_in[1];
    const float* bq = (const float*)d_in[2];
    const float* Wk = (const float*)d_in[3];
    const float* bk = (const float*)d_in[4];
    const float* Wv = (const float*)d_in[5];
    const float* bv = (const float*)d_in[6];
    const float* Wo = (const float*)d_in[7];
    const float* bo = (const float*)d_in[8];

    float* out = (float*)d_out;                       // [B,S,D]
    float* avg = out + (size_t)BB * SS * DD;          // [B,S,S]

    float* pctx;
    cudaGetSymbolAddress((void**)&pctx, g_ctx);

    cudaFuncSetAttribute(attn_fused, cudaFuncAttributeMaxDynamicSharedMemorySize,
                         FL_SMEM);
    cudaFuncSetAttribute(proj_gemm<false>, cudaFuncAttributeMaxDynamicSharedMemorySize,
                         PJ_SMEM);
    cudaFuncSetAttribute(proj_gemm<true>, cudaFuncAttributeMaxDynamicSharedMemorySize,
                         PJ_SMEM);

    dim3 blk(256);

    // 1) fused QKV projection (q,k -> bf16 hi/lo, v -> fp16)
    dim3 g1(DD/64, MM/128, 3);
    proj_gemm<false><<<g1, blk, PJ_SMEM>>>(x, Wq, Wk, Wv, bq, bk, bv, nullptr);

    // 2) fused scores+exp+ctx (writes g_p fp16, g_psum, g_ctx)
    dim3 g2(SS/128, BB*HH);
    attn_fused<<<g2, blk, FL_SMEM>>>(nullptr);

    // 3) avg_attn from E and row sums
    dim3 ga(SS, BB);
    avg_kernel<<<ga, blk>>>(avg);

    // 4) out = ctx @ Wo + bo
    dim3 g5(DD/64, MM/128, 1);
    proj_gemm<true><<<g5, blk, PJ_SMEM>>>(pctx, Wo, Wo, Wo, bo, bo, bo, out);
}

// round 14
// speedup vs baseline: 1.0357x; 1.0357x over previous
#include <cuda_runtime.h>
#include <cuda_bf16.h>
#include <cuda_fp16.h>
#include <math.h>

// Problem dims (fixed by the dataset)
#define BB  4
#define SS  2048
#define DD  512
#define HH  8
#define HD  64
#define MM  (BB*SS)          // 8192
#define NKB 16               // k-blocks per scores row (2048/128)

// Scratch (allocation-free rule: __device__ globals)
__device__ __align__(16) __nv_bfloat16 g_qh[(size_t)MM * DD];
__device__ __align__(16) __nv_bfloat16 g_ql[(size_t)MM * DD];
__device__ __align__(16) __nv_bfloat16 g_kh[(size_t)MM * DD];
__device__ __align__(16) __nv_bfloat16 g_kl[(size_t)MM * DD];
__device__ __align__(16) __half g_vh[(size_t)MM * DD];            // fp16 V
__device__ float  g_ctx [(size_t)MM * DD];
__device__ __align__(16) __half g_p[(size_t)BB * HH * SS * SS];   // fp16 exp(scores), 268MB
__device__ float  g_psum[(size_t)BB * HH * SS * NKB];             // partial row sums, 4MB

// ---------------------------------------------------------------------------
// helpers
// ---------------------------------------------------------------------------
__device__ __forceinline__ void split2(float x0, float x1, unsigned& h, unsigned& l)
{
    __nv_bfloat162 hb = __floats2bfloat162_rn(x0, x1);
    float2 hf = __bfloat1622float2(hb);
    __nv_bfloat162 lb = __floats2bfloat162_rn(x0 - hf.x, x1 - hf.y);
    h = *reinterpret_cast<unsigned*>(&hb);
    l = *reinterpret_cast<unsigned*>(&lb);
}

__device__ __forceinline__ void mma16816(float c[4],
    unsigned a0, unsigned a1, unsigned a2, unsigned a3,
    unsigned b0, unsigned b1)
{
    asm volatile(
        "mma.sync.aligned.m16n8k16.row.col.f32.bf16.bf16.f32 "
        "{%0,%1,%2,%3},{%4,%5,%6,%7},{%8,%9},{%0,%1,%2,%3};"
        : "+f"(c[0]), "+f"(c[1]), "+f"(c[2]), "+f"(c[3])
        : "r"(a0), "r"(a1), "r"(a2), "r"(a3), "r"(b0), "r"(b1));
}
__device__ __forceinline__ void mma16816_f16(float c[4],
    unsigned a0, unsigned a1, unsigned a2, unsigned a3,
    unsigned b0, unsigned b1)
{
    asm volatile(
        "mma.sync.aligned.m16n8k16.row.col.f32.f16.f16.f32 "
        "{%0,%1,%2,%3},{%4,%5,%6,%7},{%8,%9},{%0,%1,%2,%3};"
        : "+f"(c[0]), "+f"(c[1]), "+f"(c[2]), "+f"(c[3])
        : "r"(a0), "r"(a1), "r"(a2), "r"(a3), "r"(b0), "r"(b1));
}
__device__ __forceinline__ unsigned smem_u32(const void* p)
{
    return (unsigned)__cvta_generic_to_shared(p);
}
__device__ __forceinline__ void ldsm_x4(unsigned& r0, unsigned& r1,
                                        unsigned& r2, unsigned& r3, unsigned a)
{
    asm volatile("ldmatrix.sync.aligned.m8n8.x4.shared.b16 {%0,%1,%2,%3}, [%4];"
        : "=r"(r0), "=r"(r1), "=r"(r2), "=r"(r3) : "r"(a));
}
__device__ __forceinline__ void ldsm_x4_t(unsigned& r0, unsigned& r1,
                                          unsigned& r2, unsigned& r3, unsigned a)
{
    asm volatile("ldmatrix.sync.aligned.m8n8.x4.trans.shared.b16 {%0,%1,%2,%3}, [%4];"
        : "=r"(r0), "=r"(r1), "=r"(r2), "=r"(r3) : "r"(a));
}

// ---------------------------------------------------------------------------
// Projection GEMM (round-11): BM=128, BN=64, BKT=32, ldsm, double-buffered.
// ---------------------------------------------------------------------------
#define PJ_LDA 40
#define PJ_LDB 72
#define PJ_A_STAGE (128 * PJ_LDA)
#define PJ_B_STAGE (32 * PJ_LDB)
#define PJ_SMEM ((2*PJ_A_STAGE*2 + 2*PJ_B_STAGE*2) * 2)

template<bool OUT_PROJ>
__global__ void __launch_bounds__(256, 2)
proj_gemm(const float* __restrict__ A,
          const float* __restrict__ W0, const float* __restrict__ W1,
          const float* __restrict__ W2,
          const float* __restrict__ b0, const float* __restrict__ b1,
          const float* __restrict__ b2,
          float* __restrict__ outf)
{
    extern __shared__ __align__(16) char pmem[];
    __nv_bfloat16* Ah = (__nv_bfloat16*)pmem;
    __nv_bfloat16* Al = Ah + 2 * PJ_A_STAGE;
    __nv_bfloat16* Bh = Al + 2 * PJ_A_STAGE;
    __nv_bfloat16* Bl = Bh + 2 * PJ_B_STAGE;

    const int zz = blockIdx.z;
    const float* B    = (zz == 0) ? W0 : (zz == 1) ? W1 : W2;
    const float* bias = (zz == 0) ? b0 : (zz == 1) ? b1 : b2;

    const int tid   = threadIdx.x;
    const int warp  = tid >> 5;
    const int lane  = tid & 31;
    const int g     = lane >> 2;
    const int tq    = lane & 3;
    const int warpM = warp >> 2;
    const int warpN = warp & 3;
    const int m0    = blockIdx.y * 128;
    const int n0    = blockIdx.x * 64;

    const int a_row = (lane & 7) + ((lane >> 3) & 1) * 8;
    const int a_col = (lane >> 4) * 8;
    const int b_krw = a_row;
    const int b_col = warpN * 16 + (lane >> 4) * 8;

    float acc[4][2][4] = {};
    float4 pa[4], pb[2];

    auto load_t = [&](int kt) {
        #pragma unroll
        for (int j = 0; j < 4; j++) {
            int idx = tid + j * 256;
            int r = idx >> 3;
            int c = (idx & 7) << 2;
            pa[j] = *(const float4*)&A[(size_t)(m0 + r) * DD + kt + c];
        }
        #pragma unroll
        for (int j = 0; j < 2; j++) {
            int idx = tid + j * 256;
            int k = idx >> 4;
            int c = (idx & 15) << 2;
            pb[j] = *(const float4*)&B[(size_t)(kt + k) * DD + n0 + c];
        }
    };
    auto store_t = [&](int s) {
        __nv_bfloat16* Aph = Ah + s * PJ_A_STAGE;
        __nv_bfloat16* Apl = Al + s * PJ_A_STAGE;
        __nv_bfloat16* Bph = Bh + s * PJ_B_STAGE;
        __nv_bfloat16* Bpl = Bl + s * PJ_B_STAGE;
        #pragma unroll
        for (int j = 0; j < 4; j++) {
            int idx = tid + j * 256;
            int r = idx >> 3;
            int c = (idx & 7) << 2;
            unsigned h01, l01, h23, l23;
            split2(pa[j].x, pa[j].y, h01, l01);
            split2(pa[j].z, pa[j].w, h23, l23);
            *(unsigned*)&Aph[r * PJ_LDA + c]     = h01;
            *(unsigned*)&Aph[r * PJ_LDA + c + 2] = h23;
            *(unsigned*)&Apl[r * PJ_LDA + c]     = l01;
            *(unsigned*)&Apl[r * PJ_LDA + c + 2] = l23;
        }
        #pragma unroll
        for (int j = 0; j < 2; j++) {
            int idx = tid + j * 256;
            int k = idx >> 4;
            int c = (idx & 15) << 2;
            unsigned h01, l01, h23, l23;
            split2(pb[j].x, pb[j].y, h01, l01);
            split2(pb[j].z, pb[j].w, h23, l23);
            *(unsigned*)&Bph[k * PJ_LDB + c]     = h01;
            *(unsigned*)&Bph[k * PJ_LDB + c + 2] = h23;
            *(unsigned*)&Bpl[k * PJ_LDB + c]     = l01;
            *(unsigned*)&Bpl[k * PJ_LDB + c + 2] = l23;
        }
    };

    const int NKT = DD / 32;
    load_t(0);
    store_t(0);
    load_t(32);
    __syncthreads();

    for (int kt = 0; kt < NKT; kt++) {
        const int buf = kt & 1;
        if (kt + 1 < NKT) store_t(buf ^ 1);
        if (kt + 2 < NKT) load_t((kt + 2) * 32);

        const __nv_bfloat16* Aph = Ah + buf * PJ_A_STAGE;
        const __nv_bfloat16* Apl = Al + buf * PJ_A_STAGE;
        const __nv_bfloat16* Bph = Bh + buf * PJ_B_STAGE;
        const __nv_bfloat16* Bpl = Bl + buf * PJ_B_STAGE;

        #pragma unroll
        for (int ks = 0; ks < 2; ks++) {
            const int k0 = ks * 16;
            unsigned afh[4][4], afl[4][4], bfh[2][2], bfl[2][2];
            #pragma unroll
            for (int mt = 0; mt < 4; mt++) {
                int row = warpM * 64 + mt * 16 + a_row;
                ldsm_x4(afh[mt][0], afh[mt][1], afh[mt][2], afh[mt][3],
                        smem_u32(&Aph[row * PJ_LDA + k0 + a_col]));
                ldsm_x4(afl[mt][0], afl[mt][1], afl[mt][2], afl[mt][3],
                        smem_u32(&Apl[row * PJ_LDA + k0 + a_col]));
            }
            ldsm_x4_t(bfh[0][0], bfh[0][1], bfh[1][0], bfh[1][1],
                      smem_u32(&Bph[(k0 + b_krw) * PJ_LDB + b_col]));
            ldsm_x4_t(bfl[0][0], bfl[0][1], bfl[1][0], bfl[1][1],
                      smem_u32(&Bpl[(k0 + b_krw) * PJ_LDB + b_col]));

            #pragma unroll
            for (int mt = 0; mt < 4; mt++)
                #pragma unroll
                for (int nt = 0; nt < 2; nt++) {
                    mma16816(acc[mt][nt], afh[mt][0], afh[mt][1], afh[mt][2], afh[mt][3],
                             bfh[nt][0], bfh[nt][1]);
                    mma16816(acc[mt][nt], afh[mt][0], afh[mt][1], afh[mt][2], afh[mt][3],
                             bfl[nt][0], bfl[nt][1]);
                    mma16816(acc[mt][nt], afl[mt][0], afl[mt][1], afl[mt][2], afl[mt][3],
                             bfh[nt][0], bfh[nt][1]);
                }
        }
        __syncthreads();
    }

    #pragma unroll
    for (int mt = 0; mt < 4; mt++) {
        int r0 = m0 + warpM * 64 + mt * 16 + g;
        #pragma unroll
        for (int nt = 0; nt < 2; nt++) {
            int c = n0 + warpN * 16 + nt * 8 + 2 * tq;
            float bx = bias[c], by = bias[c + 1];
            float v00 = acc[mt][nt][0] + bx, v01 = acc[mt][nt][1] + by;
            float v10 = acc[mt][nt][2] + bx, v11 = acc[mt][nt][3] + by;
            size_t i0 = (size_t)r0 * DD + c;
            size_t i1 = (size_t)(r0 + 8) * DD + c;
            if (OUT_PROJ) {
                *(float2*)&outf[i0] = make_float2(v00, v01);
                *(float2*)&outf[i1] = make_float2(v10, v11);
            } else if (zz == 2) {
                *(__half2*)&g_vh[i0] = __floats2half2_rn(v00, v01);
                *(__half2*)&g_vh[i1] = __floats2half2_rn(v10, v11);
            } else {
                __nv_bfloat16* Oh = (zz == 0) ? g_qh : g_kh;
                __nv_bfloat16* Ol = (zz == 0) ? g_ql : g_kl;
                unsigned h0, l0, h1, l1;
                split2(v00, v01, h0, l0);
                split2(v10, v11, h1, l1);
                *(unsigned*)&Oh[i0] = h0;  *(unsigned*)&Ol[i0] = l0;
                *(unsigned*)&Oh[i1] = h1;  *(unsigned*)&Ol[i1] = l1;
            }
        }
    }
}

// ---------------------------------------------------------------------------
// Scores kernel (round-11): E = exp(scale*QK^T) fp16 + psums. ldmatrix frags.
// ---------------------------------------------------------------------------
#define SC_LD 72
#define SC_TILE (128 * SC_LD)
#define SC_SMEM (4 * SC_TILE * 2 + 128 * 5 * 4)

__global__ void __launch_bounds__(256, 2)
scores_exp()
{
    extern __shared__ __align__(16) char smem[];
    __nv_bfloat16* Qh = (__nv_bfloat16*)smem;
    __nv_bfloat16* Ql = Qh + SC_TILE;
    __nv_bfloat16* Kh = Ql + SC_TILE;
    __nv_bfloat16* Kl = Kh + SC_TILE;
    float (*srow)[5]  = (float(*)[5])(Kl + SC_TILE);

    const int z = blockIdx.z;
    const int b = z >> 3, h = z & 7;
    const size_t qoff = ((size_t)(b * SS + blockIdx.y * 128)) * DD + h * HD;
    const size_t koff = ((size_t)(b * SS + blockIdx.x * 128)) * DD + h * HD;

    const int tid   = threadIdx.x;
    const int warp  = tid >> 5;
    const int lane  = tid & 31;
    const int g     = lane >> 2;
    const int tq    = lane & 3;
    const int warpM = warp >> 2;
    const int warpN = warp & 3;
    const int m0    = blockIdx.y * 128;
    const int n0    = blockIdx.x * 128;

    const int a_row = (lane & 7) + ((lane >> 3) & 1) * 8;
    const int a_col = (lane >> 4) * 8;

    #pragma unroll
    for (int j = 0; j < 4; j++) {
        int idx = tid + j * 256;
        int r = idx >> 3;
        int c = (idx & 7) << 3;
        *(uint4*)&Qh[r * SC_LD + c] = *(const uint4*)&g_qh[qoff + (size_t)r * DD + c];
        *(uint4*)&Ql[r * SC_LD + c] = *(const uint4*)&g_ql[qoff + (size_t)r * DD + c];
        *(uint4*)&Kh[r * SC_LD + c] = *(const uint4*)&g_kh[koff + (size_t)r * DD + c];
        *(uint4*)&Kl[r * SC_LD + c] = *(const uint4*)&g_kl[koff + (size_t)r * DD + c];
    }
    __syncthreads();

    float acc[4][4][4] = {};

    #pragma unroll
    for (int ks = 0; ks < 4; ks++) {
        const int k0 = ks * 16;
        unsigned afh[4][4], afl[4][4], bfh[4][2], bfl[4][2];
        #pragma unroll
        for (int mt = 0; mt < 4; mt++) {
            int row = warpM * 64 + mt * 16 + a_row;
            ldsm_x4(afh[mt][0], afh[mt][1], afh[mt][2], afh[mt][3],
                    smem_u32(&Qh[row * SC_LD + k0 + a_col]));
            ldsm_x4(afl[mt][0], afl[mt][1], afl[mt][2], afl[mt][3],
                    smem_u32(&Ql[row * SC_LD + k0 + a_col]));
        }
        #pragma unroll
        for (int ng = 0; ng < 2; ng++) {
            int nrow = warpN * 32 + ng * 16 + a_row;
            ldsm_x4(bfh[2*ng][0], bfh[2*ng+1][0], bfh[2*ng][1], bfh[2*ng+1][1],
                    smem_u32(&Kh[nrow * SC_LD + k0 + a_col]));
            ldsm_x4(bfl[2*ng][0], bfl[2*ng+1][0], bfl[2*ng][1], bfl[2*ng+1][1],
                    smem_u32(&Kl[nrow * SC_LD + k0 + a_col]));
        }
        #pragma unroll
        for (int mt = 0; mt < 4; mt++)
            #pragma unroll
            for (int nt = 0; nt < 4; nt++) {
                mma16816(acc[mt][nt], afh[mt][0], afh[mt][1], afh[mt][2], afh[mt][3],
                         bfh[nt][0], bfh[nt][1]);
                mma16816(acc[mt][nt], afh[mt][0], afh[mt][1], afh[mt][2], afh[mt][3],
                         bfl[nt][0], bfl[nt][1]);
                mma16816(acc[mt][nt], afl[mt][0], afl[mt][1], afl[mt][2], afl[mt][3],
                         bfh[nt][0], bfh[nt][1]);
            }
    }

    __half* Ez = g_p + (size_t)z * SS * SS;
    #pragma unroll
    for (int mt = 0; mt < 4; mt++) {
        int rl = warpM * 64 + mt * 16 + g;
        float sA = 0.f, sB = 0.f;
        #pragma unroll
        for (int nt = 0; nt < 4; nt++) {
            int c = n0 + warpN * 32 + nt * 8 + 2 * tq;
            float e0 = __expf(acc[mt][nt][0] * 0.125f);
            float e1 = __expf(acc[mt][nt][1] * 0.125f);
            float e2 = __expf(acc[mt][nt][2] * 0.125f);
            float e3 = __expf(acc[mt][nt][3] * 0.125f);
            sA += e0 + e1;
            sB += e2 + e3;
            *(__half2*)&Ez[(size_t)(m0 + rl) * SS + c]     = __floats2half2_rn(e0, e1);
            *(__half2*)&Ez[(size_t)(m0 + rl + 8) * SS + c] = __floats2half2_rn(e2, e3);
        }
        sA += __shfl_xor_sync(0xffffffffu, sA, 1);
        sA += __shfl_xor_sync(0xffffffffu, sA, 2);
        sB += __shfl_xor_sync(0xffffffffu, sB, 1);
        sB += __shfl_xor_sync(0xffffffffu, sB, 2);
        if (tq == 0) {
            srow[rl][warpN]     = sA;
            srow[rl + 8][warpN] = sB;
        }
    }
    __syncthreads();
    if (tid < 128) {
        float s = srow[tid][0] + srow[tid][1] + srow[tid][2] + srow[tid][3];
        g_psum[((size_t)z * SS + m0 + tid) * NKB + blockIdx.x] = s;
    }
}

// ---------------------------------------------------------------------------
// avg_attn (round-11): per (b,q) row, avg_h E[z][q][:] / (8 * S[z][q]).
// ---------------------------------------------------------------------------
__global__ void __launch_bounds__(256)
avg_kernel(float* __restrict__ avg_out)
{
    const int q = blockIdx.x;
    const int b = blockIdx.y;
    const int tid = threadIdx.x;

    __shared__ float sInv[HH];
    if (tid < 128) {
        int hh = tid >> 4, j = tid & 15;
        float v = g_psum[(((size_t)(b * HH + hh)) * SS + q) * NKB + j];
        v += __shfl_xor_sync(0xffffffffu, v, 1);
        v += __shfl_xor_sync(0xffffffffu, v, 2);
        v += __shfl_xor_sync(0xffffffffu, v, 4);
        v += __shfl_xor_sync(0xffffffffu, v, 8);
        if (j == 0) sInv[hh] = 0.125f / v;
    }
    __syncthreads();

    const int c0 = tid * 8;
    float av[8] = {};
    #pragma unroll
    for (int h = 0; h < HH; h++) {
        const __half* E = g_p + ((size_t)(b * HH + h) * SS + q) * SS;
        float inv = sInv[h];
        uint4 v = *(const uint4*)&E[c0];
        const __half2* hp = (const __half2*)&v;
        #pragma unroll
        for (int j = 0; j < 4; j++) {
            float2 f = __half22float2(hp[j]);
            av[2*j]   += f.x * inv;
            av[2*j+1] += f.y * inv;
        }
    }
    float* arow = avg_out + ((size_t)b * SS + q) * SS;
    *(float4*)&arow[c0]     = make_float4(av[0], av[1], av[2], av[3]);
    *(float4*)&arow[c0 + 4] = make_float4(av[4], av[5], av[6], av[7]);
}

// ---------------------------------------------------------------------------
// ctx = (E @ V) / S (round-11): CBK=64, 2-stage double buffer, ldmatrix.
// ---------------------------------------------------------------------------
#define CLD2 72
#define CTX_A_STAGE (128 * CLD2)
#define CTX_B_STAGE (64 * CLD2)
#define CTX_SMEM (2 * (CTX_A_STAGE + CTX_B_STAGE) * 2 + 128 * 4)

__global__ void __launch_bounds__(256, 2)
ctx_f16()
{
    extern __shared__ __align__(16) char cmem[];
    __half* As   = (__half*)cmem;
    __half* Bs   = As + 2 * CTX_A_STAGE;
    float*  sInv = (float*)(Bs + 2 * CTX_B_STAGE);

    const int z = blockIdx.z;
    const int b = z >> 3, h = z & 7;
    const __half* P = g_p  + (size_t)z * SS * SS;
    const __half* V = g_vh + (size_t)b * SS * DD + h * HD;
    float*        C = g_ctx + (size_t)b * SS * DD + h * HD;

    const int tid   = threadIdx.x;
    const int warp  = tid >> 5;
    const int lane  = tid & 31;
    const int g     = lane >> 2;
    const int tq    = lane & 3;
    const int warpM = warp >> 2;
    const int warpN = warp & 3;
    const int m0    = blockIdx.y * 128;

    {
        int r = tid >> 1, j0 = (tid & 1) * 8;
        const float* ps = &g_psum[((size_t)z * SS + m0 + r) * NKB + j0];
        float s = 0.f;
        #pragma unroll
        for (int j = 0; j < 8; j++) s += ps[j];
        s += __shfl_xor_sync(0xffffffffu, s, 1);
        if ((tid & 1) == 0) sInv[r] = 1.f / s;
    }

    const int a_row = (lane & 7) + ((lane >> 3) & 1) * 8;
    const int a_col = (lane >> 4) * 8;
    const int b_krw = a_row;
    const int b_col = warpN * 16 + (lane >> 4) * 8;

    uint4 pa[4], pb[2];
    auto load_t = [&](int kt) {
        #pragma unroll
        for (int j = 0; j < 4; j++) {
            int idx = tid + j * 256;
            int r = idx >> 3;
            int c = (idx & 7) << 3;
            pa[j] = *(const uint4*)&P[(size_t)(m0 + r) * SS + kt + c];
        }
        #pragma unroll
        for (int j = 0; j < 2; j++) {
            int idx = tid + j * 256;
            int k = idx >> 3;
            int c = (idx & 7) << 3;
            pb[j] = *(const uint4*)&V[(size_t)(kt + k) * DD + c];
        }
    };
    auto store_t = [&](int s) {
        __half* Ap = As + s * CTX_A_STAGE;
        __half* Bp = Bs + s * CTX_B_STAGE;
        #pragma unroll
        for (int j = 0; j < 4; j++) {
            int idx = tid + j * 256;
            int r = idx >> 3;
            int c = (idx & 7) << 3;
            *(uint4*)&Ap[r * CLD2 + c] = pa[j];
        }
        #pragma unroll
        for (int j = 0; j < 2; j++) {
            int idx = tid + j * 256;
            int k = idx >> 3;
            int c = (idx & 7) << 3;
            *(uint4*)&Bp[k * CLD2 + c] = pb[j];
        }
    };

    float acc[4][2][4] = {};

    const int NIT = SS / 64;
    load_t(0);
    store_t(0);
    load_t(64);
    __syncthreads();

    for (int kt = 0; kt < NIT; kt++) {
        const int buf = kt & 1;
        if (kt + 1 < NIT) store_t(buf ^ 1);
        if (kt + 2 < NIT) load_t((kt + 2) * 64);

        const __half* Ap = As + buf * CTX_A_STAGE;
        const __half* Bp = Bs + buf * CTX_B_STAGE;

        #pragma unroll
        for (int ks = 0; ks < 4; ks++) {
            const int k0 = ks * 16;
            unsigned af[4][4], bf[2][2];
            #pragma unroll
            for (int mt = 0; mt < 4; mt++) {
                int row = warpM * 64 + mt * 16 + a_row;
                ldsm_x4(af[mt][0], af[mt][1], af[mt][2], af[mt][3],
                        smem_u32(&Ap[row * CLD2 + k0 + a_col]));
            }
            ldsm_x4_t(bf[0][0], bf[0][1], bf[1][0], bf[1][1],
                      smem_u32(&Bp[(k0 + b_krw) * CLD2 + b_col]));
            #pragma unroll
            for (int mt = 0; mt < 4; mt++)
                #pragma unroll
                for (int nt = 0; nt < 2; nt++)
                    mma16816_f16(acc[mt][nt], af[mt][0], af[mt][1], af[mt][2], af[mt][3],
                                 bf[nt][0], bf[nt][1]);
        }
        __syncthreads();
    }

    #pragma unroll
    for (int mt = 0; mt < 4; mt++) {
        int rl = warpM * 64 + mt * 16 + g;
        float iv0 = sInv[rl];
        float iv1 = sInv[rl + 8];
        #pragma unroll
        for (int nt = 0; nt < 2; nt++) {
            int c = warpN * 16 + nt * 8 + 2 * tq;
            *(float2*)&C[(size_t)(m0 + rl) * DD + c] =
                make_float2(acc[mt][nt][0] * iv0, acc[mt][nt][1] * iv0);
            *(float2*)&C[(size_t)(m0 + rl + 8) * DD + c] =
                make_float2(acc[mt][nt][2] * iv1, acc[mt][nt][3] * iv1);
        }
    }
}

// ---------------------------------------------------------------------------
extern "C" void kernel_launch(void* const* d_in, const int* in_sizes, int n_in,
                              void* d_out, int out_size)
{
    const float* x  = (const float*)d_in[0];
    const float* Wq = (const float*)d_in[1];
    const float* bq = (const float*)d_in[2];
    const float* Wk = (const float*)d_in[3];
    const float* bk = (const float*)d_in[4];
    const float* Wv = (const float*)d_in[5];
    const float* bv = (const float*)d_in[6];
    const float* Wo = (const float*)d_in[7];
    const float* bo = (const float*)d_in[8];

    float* out = (float*)d_out;                       // [B,S,D]
    float* avg = out + (size_t)BB * SS * DD;          // [B,S,S]

    float* pctx;
    cudaGetSymbolAddress((void**)&pctx, g_ctx);

    cudaFuncSetAttribute(scores_exp, cudaFuncAttributeMaxDynamicSharedMemorySize,
                         SC_SMEM);
    cudaFuncSetAttribute(ctx_f16, cudaFuncAttributeMaxDynamicSharedMemorySize,
                         CTX_SMEM);
    cudaFuncSetAttribute(proj_gemm<false>, cudaFuncAttributeMaxDynamicSharedMemorySize,
                         PJ_SMEM);
    cudaFuncSetAttribute(proj_gemm<true>, cudaFuncAttributeMaxDynamicSharedMemorySize,
                         PJ_SMEM);

    // side stream + fork/join events for avg ∥ (ctx -> out) overlap.
    // Host-object creation only (no device memory); leaked intentionally —
    // kernel_launch is invoked a handful of times (correctness + capture).
    cudaStream_t side;
    cudaStreamCreateWithFlags(&side, cudaStreamNonBlocking);
    cudaEvent_t evFork, evJoin;
    cudaEventCreateWithFlags(&evFork, cudaEventDisableTiming);
    cudaEventCreateWithFlags(&evJoin, cudaEventDisableTiming);

    dim3 blk(256);

    // 1) fused QKV projection (q,k -> bf16 hi/lo, v -> fp16)
    dim3 g1(DD/64, MM/128, 3);
    proj_gemm<false><<<g1, blk, PJ_SMEM>>>(x, Wq, Wk, Wv, bq, bk, bv, nullptr);

    // 2) E = exp(scale * Q K^T) -> fp16 + partial row sums
    dim3 g2(SS/128, SS/128, BB*HH);
    scores_exp<<<g2, blk, SC_SMEM>>>();

    // fork: avg on side stream, concurrent with ctx + out-proj on main
    cudaEventRecord(evFork, 0);
    cudaStreamWaitEvent(side, evFork, 0);

    dim3 ga(SS, BB);
    avg_kernel<<<ga, blk, 0, side>>>(avg);

    // 3) ctx = (E @ V) / S  (main stream)
    dim3 g3(1, SS/128, BB*HH);
    ctx_f16<<<g3, blk, CTX_SMEM>>>();

    // 4) out = ctx @ Wo + bo  (main stream)
    dim3 g5(DD/64, MM/128, 1);
    proj_gemm<true><<<g5, blk, PJ_SMEM>>>(pctx, Wo, Wo, Wo, bo, bo, bo, out);

    // join: main stream completion depends on avg
    cudaEventRecord(evJoin, side);
    cudaStreamWaitEvent(0, evJoin, 0);
}